// round 14
// baseline (speedup 1.0000x reference)
#include <cuda_runtime.h>
#include <cuda_bf16.h>
#include <cstdint>

#define NN 100000
#define NE 640000
#define NL 100000
#define SCAN_BLK 512
#define NSCAN ((NN + SCAN_BLK - 1) / SCAN_BLK)

// Scratch (device globals: allocation-free rule)
__device__ float g_agg[(size_t)NN * 128];     // layer-1 mean aggregate
__device__ float g_hpre[(size_t)NN * 128];    // x @ W1r^T (self term)
__device__ float g_h[(size_t)NN * 128];
__device__ float g_pq[(size_t)NN * 128];      // [p | q] = h @ [W2l | W2r]^T
__device__ float g_z[(size_t)NN * 64];
// CSR scratch
__device__ int g_deg[NN];
__device__ int g_excl[NN];
__device__ int g_bsum[NSCAN];
__device__ int g_rowptr[NN + 1];
__device__ int g_cursor[NN];
__device__ int g_srcs[NE];

// ---------------------------------------------------------------------------
__device__ __forceinline__ uint32_t smem_u32(const void* p) {
    uint32_t a;
    asm("{ .reg .u64 t; cvta.to.shared.u64 t, %1; cvt.u32.u64 %0, t; }" : "=r"(a) : "l"(p));
    return a;
}

__device__ __forceinline__ void cp_async16(uint32_t saddr, const void* gaddr, int src_size) {
    asm volatile("cp.async.cg.shared.global [%0], [%1], 16, %2;"
                 :: "r"(saddr), "l"(gaddr), "r"(src_size) : "memory");
}
#define CP_COMMIT() asm volatile("cp.async.commit_group;" ::: "memory")
#define CP_WAIT(N)  asm volatile("cp.async.wait_group %0;" :: "n"(N) : "memory")

__device__ __forceinline__ uint32_t f2tf32(float v) {
    uint32_t t;
    asm("cvt.rna.tf32.f32 %0, %1;" : "=r"(t) : "f"(v));
    return t;
}

// m16n8k8 tf32 mma, fp32 accumulate in place (row.col)
__device__ __forceinline__ void mma_tf32(float* c, uint32_t a0, uint32_t a1,
                                         uint32_t a2, uint32_t a3,
                                         uint32_t b0, uint32_t b1) {
    asm volatile(
        "mma.sync.aligned.m16n8k8.row.col.f32.tf32.tf32.f32 "
        "{%0,%1,%2,%3}, {%4,%5,%6,%7}, {%8,%9}, {%0,%1,%2,%3};"
        : "+f"(c[0]), "+f"(c[1]), "+f"(c[2]), "+f"(c[3])
        : "r"(a0), "r"(a1), "r"(a2), "r"(a3), "r"(b0), "r"(b1));
}

// A stage: K=128 fp32 row (512B) + 16B pad (528 -> LDS.32 conflict-free)
#define ASTR 528
#define ASZ  (128 * ASTR)   // one stage = 67584 B
// B tile: K=128 tf32 row (512B) + 32B pad (544 -> phase-conflict-free LDS.64)
#define BSTR 544
#define SB   (128 * BSTR)   // 69632 B

// Weight tile conversion into smem: tf32, per-k8-group word order
// (k0,k4)(k1,k5)(k2,k6)(k3,k7) so the m16n8k8 B fragment {k, k+4} is one LDS.64.
__device__ __forceinline__ void convert_weights(
    uint8_t* sB,
    const float* __restrict__ Wa, const float* __restrict__ Wb,
    int tid, int nthreads)
{
    for (int idx = tid; idx < 128 * 32; idx += nthreads) {
        int row = idx >> 5;
        int k = (idx & 31) * 4;                 // 0,4,8,...,124
        const float* wsrc = ((row < 64) ? (Wa + (size_t)row * 128)
                                        : (Wb + (size_t)(row - 64) * 128)) + k;
        float4 v = __ldg(reinterpret_cast<const float4*>(wsrc));
        uint32_t t0 = f2tf32(v.x), t1 = f2tf32(v.y), t2 = f2tf32(v.z), t3 = f2tf32(v.w);
        const int base = row * BSTR + (k >> 3) * 32;   // 32B per k8 group
        const int half = (k & 7) >> 2;                 // 0: b0 slots, 1: b1 slots
        *reinterpret_cast<uint32_t*>(sB + base + 0 * 8 + half * 4) = t0;
        *reinterpret_cast<uint32_t*>(sB + base + 1 * 8 + half * 4) = t1;
        *reinterpret_cast<uint32_t*>(sB + base + 2 * 8 + half * 4) = t2;
        *reinterpret_cast<uint32_t*>(sB + base + 3 * 8 + half * 4) = t3;
    }
}

// ===========================================================================
// Persistent K=128 TF32 GEMM: out[m, 0:128] = epi( A[m,:] @ W^T )
// W rows: row<64 from Wa, else Wb. EPI 0: identity.
// EPI 1: relu(acc + addend[m,col] + bias[col]).
// 512 threads / 16 warps, warp tile 16x64, cp.async 2-stage full-tile pipeline.
// ===========================================================================
__device__ __forceinline__ void prefetchA(
    int it, int bid, int grid, int M,
    const float* __restrict__ A, uint32_t sA_u32, int tid)
{
    const int row0 = (bid + it * grid) << 7;
    const uint32_t abase = sA_u32 + (it & 1) * ASZ;
    const float* gbase = A + (size_t)row0 * 128;
#pragma unroll
    for (int s = 0; s < 8; ++s) {
        int seg = s * 512 + tid;
        int r = seg >> 5, c = seg & 31;
        bool val = (row0 + r) < M;
        const float* g = gbase + (val ? ((size_t)r * 128 + c * 4) : 0);
        cp_async16(abase + r * ASTR + c * 16, g, val ? 16 : 0);
    }
    CP_COMMIT();
}

template <int EPI>
__global__ void __launch_bounds__(512, 1)
pgemmB_kernel(const float* __restrict__ A,
              const float* __restrict__ Wa, const float* __restrict__ Wb,
              const float* __restrict__ addend, const float* __restrict__ bias,
              float* __restrict__ out, int M)
{
    extern __shared__ uint8_t smem[];
    uint8_t* sB = smem;
    uint8_t* sA = smem + SB;

    const int tid = threadIdx.x, lane = tid & 31, wid = tid >> 5;
    const int warp_m = wid & 7, warp_n = wid >> 3;
    const int qrow = lane >> 2, lm4 = lane & 3;
    const int bid = blockIdx.x, grid = gridDim.x;
    const uint32_t sA_u32 = smem_u32(smem) + SB;

    convert_weights(sB, Wa, Wb, tid, 512);

    const int ntiles = (M + 127) >> 7;
    if (bid >= ntiles) return;
    const int nIter = (ntiles - bid + grid - 1) / grid;

    float acc[8][4] = {};

    prefetchA(0, bid, grid, M, A, sA_u32, tid);

    for (int it = 0; it < nIter; ++it) {
        if (it) __syncthreads();
        if (it + 1 < nIter) {
            prefetchA(it + 1, bid, grid, M, A, sA_u32, tid);
            CP_WAIT(1);
        } else {
            CP_WAIT(0);
        }
        __syncthreads();

        const uint8_t* aS = sA + (it & 1) * ASZ;

#pragma unroll
        for (int s = 0; s < 16; ++s) {          // 16 k8 steps
            const int r0b = (warp_m * 16 + qrow) * ASTR + (s * 8 + lm4) * 4;
            const int r8b = r0b + 8 * ASTR;
            uint32_t a0 = f2tf32(*reinterpret_cast<const float*>(aS + r0b));
            uint32_t a1 = f2tf32(*reinterpret_cast<const float*>(aS + r8b));
            uint32_t a2 = f2tf32(*reinterpret_cast<const float*>(aS + r0b + 16));
            uint32_t a3 = f2tf32(*reinterpret_cast<const float*>(aS + r8b + 16));
            const int gkb = s * 32 + lm4 * 8;
#pragma unroll
            for (int j = 0; j < 8; ++j) {
                const int nb = (warp_n * 64 + j * 8 + qrow) * BSTR + gkb;
                uint2 b = *reinterpret_cast<const uint2*>(sB + nb);
                mma_tf32(acc[j], a0, a1, a2, a3, b.x, b.y);
            }
        }

        {
            const int row0 = (bid + it * grid) << 7;
            const int r = row0 + warp_m * 16 + qrow;
#pragma unroll
            for (int j = 0; j < 8; ++j) {
                const int col = warp_n * 64 + j * 8 + lm4 * 2;
                float2 v0 = make_float2(acc[j][0], acc[j][1]);
                float2 v1 = make_float2(acc[j][2], acc[j][3]);
                if (EPI == 1) {
                    float2 bv = *reinterpret_cast<const float2*>(bias + col);
                    if (r < M) {
                        float2 a0v = __ldg(reinterpret_cast<const float2*>(
                                           addend + (size_t)r * 128 + col));
                        v0.x = fmaxf(v0.x + a0v.x + bv.x, 0.f);
                        v0.y = fmaxf(v0.y + a0v.y + bv.y, 0.f);
                    }
                    if (r + 8 < M) {
                        float2 a1v = __ldg(reinterpret_cast<const float2*>(
                                           addend + (size_t)(r + 8) * 128 + col));
                        v1.x = fmaxf(v1.x + a1v.x + bv.x, 0.f);
                        v1.y = fmaxf(v1.y + a1v.y + bv.y, 0.f);
                    }
                }
                if (r < M)
                    *reinterpret_cast<float2*>(out + (size_t)r * 128 + col) = v0;
                if (r + 8 < M)
                    *reinterpret_cast<float2*>(out + (size_t)(r + 8) * 128 + col) = v1;
                acc[j][0] = acc[j][1] = acc[j][2] = acc[j][3] = 0.f;
            }
        }
    }
}

// ===========================================================================
// CSR build: histogram -> scan (2 kernels) -> slot fill
// ===========================================================================
__global__ void zero_deg_kernel(int* deg, int n) {
    int i = blockIdx.x * blockDim.x + threadIdx.x;
    if (i < n) deg[i] = 0;
}

__global__ void hist_kernel(const int* __restrict__ ei, int* __restrict__ deg, int E) {
    int e = blockIdx.x * blockDim.x + threadIdx.x;
    if (e >= E) return;
    int d = __ldg(&ei[E + e]);
    if ((unsigned)d < NN) atomicAdd(&deg[d], 1);
}

__global__ void scan1_kernel(const int* __restrict__ deg, int* __restrict__ excl,
                             int* __restrict__ bsum, int n) {
    __shared__ int sh[SCAN_BLK];
    int b = blockIdx.x;
    int i = b * SCAN_BLK + threadIdx.x;
    int v = (i < n) ? deg[i] : 0;
    sh[threadIdx.x] = v;
    __syncthreads();
#pragma unroll
    for (int off = 1; off < SCAN_BLK; off <<= 1) {
        int t = (threadIdx.x >= off) ? sh[threadIdx.x - off] : 0;
        __syncthreads();
        sh[threadIdx.x] += t;
        __syncthreads();
    }
    if (i < n) excl[i] = sh[threadIdx.x] - v;
    if (threadIdx.x == SCAN_BLK - 1) bsum[b] = sh[SCAN_BLK - 1];
}

// scan3 with scan2 folded in: every block redundantly scans the <=256 block
// sums in smem (cheap), then applies the exclusive block offset.
__global__ void scan3_kernel(const int* __restrict__ excl, const int* __restrict__ bsum,
                             int* __restrict__ rowptr, int* __restrict__ cursor,
                             int n, int total, int nb) {
    __shared__ int sh[256];
    int t = threadIdx.x;
    int v = (t < nb) ? __ldg(&bsum[t]) : 0;
    sh[t] = v;
    __syncthreads();
#pragma unroll
    for (int off = 1; off < 256; off <<= 1) {
        int u = (t >= off) ? sh[t - off] : 0;
        __syncthreads();
        sh[t] += u;
        __syncthreads();
    }
    // sh = inclusive scan of bsum
    int i = blockIdx.x * blockDim.x + t;
    if (i < n) {
        int b = i / SCAN_BLK;
        int boffb = sh[b] - __ldg(&bsum[b]);   // exclusive offset
        int val = excl[i] + boffb;
        rowptr[i] = val;
        cursor[i] = val;
    }
    if (i == 0) rowptr[n] = total;
}

// slot fill: 2 edges per thread (independent atomic/store chains)
__global__ void fill_kernel(const int* __restrict__ ei, int* __restrict__ cursor,
                            int* __restrict__ srcs, int E) {
    int e = (blockIdx.x * blockDim.x + threadIdx.x) * 2;
#pragma unroll
    for (int u = 0; u < 2; ++u) {
        int ee = e + u;
        if (ee >= E) break;
        int s = __ldg(&ei[ee]);
        int d = __ldg(&ei[E + ee]);
        if ((unsigned)s >= NN || (unsigned)d >= NN) continue;
        int slot = atomicAdd(&cursor[d], 1);
        srcs[slot] = s;
    }
}

// ===========================================================================
// agg1: warp per node, mean of neighbor x rows; edge loop unrolled x2 for MLP
// ===========================================================================
__global__ void agg1_kernel(const float* __restrict__ x,
                            const int* __restrict__ rowptr,
                            const int* __restrict__ srcs,
                            float* __restrict__ agg) {
    int gid = blockIdx.x * blockDim.x + threadIdx.x;
    int n = gid >> 5, lane = gid & 31;
    if (n >= NN) return;
    int beg = __ldg(&rowptr[n]), end = __ldg(&rowptr[n + 1]);
    float4 acc = make_float4(0.f, 0.f, 0.f, 0.f);
    int i = beg;
    for (; i + 1 < end; i += 2) {
        int s0 = __ldg(&srcs[i]);
        int s1 = __ldg(&srcs[i + 1]);
        float4 v0 = __ldg(reinterpret_cast<const float4*>(x + (size_t)s0 * 128) + lane);
        float4 v1 = __ldg(reinterpret_cast<const float4*>(x + (size_t)s1 * 128) + lane);
        acc.x += v0.x + v1.x; acc.y += v0.y + v1.y;
        acc.z += v0.z + v1.z; acc.w += v0.w + v1.w;
    }
    if (i < end) {
        int s = __ldg(&srcs[i]);
        float4 v = __ldg(reinterpret_cast<const float4*>(x + (size_t)s * 128) + lane);
        acc.x += v.x; acc.y += v.y; acc.z += v.z; acc.w += v.w;
    }
    float sc = 1.f / fmaxf((float)(end - beg), 1.f);
    acc.x *= sc; acc.y *= sc; acc.z *= sc; acc.w *= sc;
    reinterpret_cast<float4*>(agg + (size_t)n * 128)[lane] = acc;
}

// layer-2 aggregation of p fused with combine: z = mean_p + q + b2 (unroll x2)
__global__ void agg2z_kernel(const float* __restrict__ pq,
                             const int* __restrict__ rowptr,
                             const int* __restrict__ srcs,
                             const float* __restrict__ b2,
                             float* __restrict__ z) {
    int gid = blockIdx.x * blockDim.x + threadIdx.x;
    int n = gid >> 5, lane = gid & 31;
    if (n >= NN) return;
    int beg = __ldg(&rowptr[n]), end = __ldg(&rowptr[n + 1]);
    float2 acc = make_float2(0.f, 0.f);
    int i = beg;
    for (; i + 1 < end; i += 2) {
        int s0 = __ldg(&srcs[i]);
        int s1 = __ldg(&srcs[i + 1]);
        float2 v0 = __ldg(reinterpret_cast<const float2*>(pq + (size_t)s0 * 128) + lane);
        float2 v1 = __ldg(reinterpret_cast<const float2*>(pq + (size_t)s1 * 128) + lane);
        acc.x += v0.x + v1.x; acc.y += v0.y + v1.y;
    }
    if (i < end) {
        int s = __ldg(&srcs[i]);
        float2 v = __ldg(reinterpret_cast<const float2*>(pq + (size_t)s * 128) + lane);
        acc.x += v.x; acc.y += v.y;
    }
    float sc = 1.f / fmaxf((float)(end - beg), 1.f);
    float2 q = __ldg(reinterpret_cast<const float2*>(pq + (size_t)n * 128 + 64) + lane);
    float2 bv = *reinterpret_cast<const float2*>(b2 + lane * 2);
    float2 r;
    r.x = fmaf(acc.x, sc, q.x + bv.x);
    r.y = fmaf(acc.y, sc, q.y + bv.y);
    *reinterpret_cast<float2*>(z + (size_t)n * 64 + lane * 2) = r;
}

// Decode: half-warp per pair, float4 loads
__global__ void decode_kernel(const float* __restrict__ z,
                              const int* __restrict__ eli,
                              float* __restrict__ out, int L) {
    int gid = blockIdx.x * blockDim.x + threadIdx.x;
    int e = gid >> 4;
    int l = gid & 15;
    if (e >= L) return;
    int a = __ldg(&eli[e]);
    int b = __ldg(&eli[L + e]);
    float s = 0.f;
    if ((unsigned)a < NN && (unsigned)b < NN) {
        float4 va = __ldg(reinterpret_cast<const float4*>(z + (size_t)a * 64) + l);
        float4 vb = __ldg(reinterpret_cast<const float4*>(z + (size_t)b * 64) + l);
        s = va.x * vb.x + va.y * vb.y + va.z * vb.z + va.w * vb.w;
    }
#pragma unroll
    for (int off = 8; off > 0; off >>= 1)
        s += __shfl_xor_sync(0xFFFFFFFFu, s, off);
    if (l == 0) out[e] = s;
}

// ===========================================================================
extern "C" void kernel_launch(void* const* d_in, const int* in_sizes, int n_in,
                              void* d_out, int out_size) {
    const float* x   = (const float*)d_in[0];
    const int*   ei  = (const int*)d_in[1];
    const int*   eli = (const int*)d_in[2];
    const float* W1l = (const float*)d_in[3];
    const float* b1  = (const float*)d_in[4];
    const float* W1r = (const float*)d_in[5];
    const float* W2l = (const float*)d_in[6];
    const float* b2  = (const float*)d_in[7];
    const float* W2r = (const float*)d_in[8];
    float* out = (float*)d_out;

    float *agg, *hpre, *h, *pq, *z;
    int *deg, *excl, *bsum, *rowptr, *cursor, *srcs;
    cudaGetSymbolAddress((void**)&agg,  g_agg);
    cudaGetSymbolAddress((void**)&hpre, g_hpre);
    cudaGetSymbolAddress((void**)&h,    g_h);
    cudaGetSymbolAddress((void**)&pq,   g_pq);
    cudaGetSymbolAddress((void**)&z,    g_z);
    cudaGetSymbolAddress((void**)&deg,  g_deg);
    cudaGetSymbolAddress((void**)&excl, g_excl);
    cudaGetSymbolAddress((void**)&bsum, g_bsum);
    cudaGetSymbolAddress((void**)&rowptr, g_rowptr);
    cudaGetSymbolAddress((void**)&cursor, g_cursor);
    cudaGetSymbolAddress((void**)&srcs, g_srcs);

    // smem: B tf32 (69632) + 2 A stages (135168) + pad
    const int smemB = SB + 2 * ASZ + 256;
    cudaFuncSetAttribute(pgemmB_kernel<0>, cudaFuncAttributeMaxDynamicSharedMemorySize, smemB);
    cudaFuncSetAttribute(pgemmB_kernel<1>, cudaFuncAttributeMaxDynamicSharedMemorySize, smemB);
    const int PGRID = 148;

    // Fork a side stream off the capture stream (graph fork-join pattern).
    cudaStream_t side;
    cudaStreamCreateWithFlags(&side, cudaStreamNonBlocking);
    cudaEvent_t ev_fork, ev_join;
    cudaEventCreateWithFlags(&ev_fork, cudaEventDisableTiming);
    cudaEventCreateWithFlags(&ev_join, cudaEventDisableTiming);

    cudaEventRecord(ev_fork, 0);
    cudaStreamWaitEvent(side, ev_fork, 0);

    // ---- side stream: self-term GEMM  h_pre = x @ W1r^T ----
    pgemmB_kernel<0><<<PGRID, 512, smemB, side>>>(
        x, W1r, W1r + 64 * 128, nullptr, nullptr, hpre, NN);
    cudaEventRecord(ev_join, side);

    // ---- main stream: CSR build + layer-1 aggregation (independent) ----
    zero_deg_kernel<<<(NN + 255) / 256, 256>>>(deg, NN);
    hist_kernel<<<(NE + 255) / 256, 256>>>(ei, deg, NE);
    scan1_kernel<<<NSCAN, SCAN_BLK>>>(deg, excl, bsum, NN);
    scan3_kernel<<<(NN + 255) / 256, 256>>>(excl, bsum, rowptr, cursor, NN, NE, NSCAN);
    fill_kernel<<<(NE / 2 + 255) / 256, 256>>>(ei, cursor, srcs, NE);
    agg1_kernel<<<(NN * 32 + 255) / 256, 256>>>(x, rowptr, srcs, agg);

    // ---- join, then layer-1 neighbor GEMM with fused self/bias/relu ----
    cudaStreamWaitEvent(0, ev_join, 0);
    pgemmB_kernel<1><<<PGRID, 512, smemB>>>(
        agg, W1l, W1l + 64 * 128, hpre, b1, h, NN);

    // ---- Layer 2 (projection-before-aggregation) ----
    pgemmB_kernel<0><<<PGRID, 512, smemB>>>(h, W2l, W2r, nullptr, nullptr, pq, NN);
    agg2z_kernel<<<(NN * 32 + 255) / 256, 256>>>(pq, rowptr, srcs, b2, z);

    // ---- Decode ----
    decode_kernel<<<(NL * 16 + 255) / 256, 256>>>(z, eli, out, NL);
}

// round 15
// speedup vs baseline: 1.0322x; 1.0322x over previous
#include <cuda_runtime.h>
#include <cuda_bf16.h>
#include <cstdint>

#define NN 100000
#define NE 640000
#define NL 100000
#define SCAN_BLK 512
#define NSCAN ((NN + SCAN_BLK - 1) / SCAN_BLK)

// Scratch (device globals: allocation-free rule)
__device__ float g_agg[(size_t)NN * 128];     // layer-1 mean aggregate
__device__ float g_hpre[(size_t)NN * 128];    // x @ W1r^T (self term)
__device__ float g_h[(size_t)NN * 128];
__device__ float g_pq[(size_t)NN * 128];      // [p | q] = h @ [W2l | W2r]^T
__device__ float g_z[(size_t)NN * 64];
// CSR scratch
__device__ int g_deg[NN];
__device__ int g_excl[NN];
__device__ int g_bsum[NSCAN];
__device__ int g_rowptr[NN + 1];
__device__ int g_cursor[NN];
__device__ int g_srcs[NE];

// ---------------------------------------------------------------------------
__device__ __forceinline__ uint32_t smem_u32(const void* p) {
    uint32_t a;
    asm("{ .reg .u64 t; cvta.to.shared.u64 t, %1; cvt.u32.u64 %0, t; }" : "=r"(a) : "l"(p));
    return a;
}

__device__ __forceinline__ void cp_async16(uint32_t saddr, const void* gaddr, int src_size) {
    asm volatile("cp.async.cg.shared.global [%0], [%1], 16, %2;"
                 :: "r"(saddr), "l"(gaddr), "r"(src_size) : "memory");
}
#define CP_COMMIT() asm volatile("cp.async.commit_group;" ::: "memory")
#define CP_WAIT(N)  asm volatile("cp.async.wait_group %0;" :: "n"(N) : "memory")

__device__ __forceinline__ uint32_t f2tf32(float v) {
    uint32_t t;
    asm("cvt.rna.tf32.f32 %0, %1;" : "=r"(t) : "f"(v));
    return t;
}

// m16n8k8 tf32 mma, fp32 accumulate in place (row.col)
__device__ __forceinline__ void mma_tf32(float* c, uint32_t a0, uint32_t a1,
                                         uint32_t a2, uint32_t a3,
                                         uint32_t b0, uint32_t b1) {
    asm volatile(
        "mma.sync.aligned.m16n8k8.row.col.f32.tf32.tf32.f32 "
        "{%0,%1,%2,%3}, {%4,%5,%6,%7}, {%8,%9}, {%0,%1,%2,%3};"
        : "+f"(c[0]), "+f"(c[1]), "+f"(c[2]), "+f"(c[3])
        : "r"(a0), "r"(a1), "r"(a2), "r"(a3), "r"(b0), "r"(b1));
}

// A stage: K=128 fp32 row (512B) + 16B pad (528 -> LDS.32 conflict-free)
#define ASTR 528
#define ASZ  (128 * ASTR)   // one stage = 67584 B
// B tile: K=128 tf32 row (512B) + 32B pad (544 -> phase-conflict-free LDS.64)
#define BSTR 544
#define SB   (128 * BSTR)   // 69632 B

// Weight tile conversion into smem: tf32, per-k8-group word order
// (k0,k4)(k1,k5)(k2,k6)(k3,k7) so the m16n8k8 B fragment {k, k+4} is one LDS.64.
__device__ __forceinline__ void convert_weights(
    uint8_t* sB,
    const float* __restrict__ Wa, const float* __restrict__ Wb,
    int tid, int nthreads)
{
    for (int idx = tid; idx < 128 * 32; idx += nthreads) {
        int row = idx >> 5;
        int k = (idx & 31) * 4;                 // 0,4,8,...,124
        const float* wsrc = ((row < 64) ? (Wa + (size_t)row * 128)
                                        : (Wb + (size_t)(row - 64) * 128)) + k;
        float4 v = __ldg(reinterpret_cast<const float4*>(wsrc));
        uint32_t t0 = f2tf32(v.x), t1 = f2tf32(v.y), t2 = f2tf32(v.z), t3 = f2tf32(v.w);
        const int base = row * BSTR + (k >> 3) * 32;   // 32B per k8 group
        const int half = (k & 7) >> 2;                 // 0: b0 slots, 1: b1 slots
        *reinterpret_cast<uint32_t*>(sB + base + 0 * 8 + half * 4) = t0;
        *reinterpret_cast<uint32_t*>(sB + base + 1 * 8 + half * 4) = t1;
        *reinterpret_cast<uint32_t*>(sB + base + 2 * 8 + half * 4) = t2;
        *reinterpret_cast<uint32_t*>(sB + base + 3 * 8 + half * 4) = t3;
    }
}

// ===========================================================================
// Persistent K=128 TF32 GEMM: out[m, 0:128] = epi( A[m,:] @ W^T )
// W rows: row<64 from Wa, else Wb. EPI 0: identity.
// EPI 1: relu(acc + addend[m,col] + bias[col]).
// 512 threads / 16 warps, warp tile 16x64, cp.async 2-stage full-tile pipeline.
// ===========================================================================
__device__ __forceinline__ void prefetchA(
    int it, int bid, int grid, int M,
    const float* __restrict__ A, uint32_t sA_u32, int tid)
{
    const int row0 = (bid + it * grid) << 7;
    const uint32_t abase = sA_u32 + (it & 1) * ASZ;
    const float* gbase = A + (size_t)row0 * 128;
#pragma unroll
    for (int s = 0; s < 8; ++s) {
        int seg = s * 512 + tid;
        int r = seg >> 5, c = seg & 31;
        bool val = (row0 + r) < M;
        const float* g = gbase + (val ? ((size_t)r * 128 + c * 4) : 0);
        cp_async16(abase + r * ASTR + c * 16, g, val ? 16 : 0);
    }
    CP_COMMIT();
}

template <int EPI>
__global__ void __launch_bounds__(512, 1)
pgemmB_kernel(const float* __restrict__ A,
              const float* __restrict__ Wa, const float* __restrict__ Wb,
              const float* __restrict__ addend, const float* __restrict__ bias,
              float* __restrict__ out, int M)
{
    extern __shared__ uint8_t smem[];
    uint8_t* sB = smem;
    uint8_t* sA = smem + SB;

    const int tid = threadIdx.x, lane = tid & 31, wid = tid >> 5;
    const int warp_m = wid & 7, warp_n = wid >> 3;
    const int qrow = lane >> 2, lm4 = lane & 3;
    const int bid = blockIdx.x, grid = gridDim.x;
    const uint32_t sA_u32 = smem_u32(smem) + SB;

    convert_weights(sB, Wa, Wb, tid, 512);

    const int ntiles = (M + 127) >> 7;
    if (bid >= ntiles) return;
    const int nIter = (ntiles - bid + grid - 1) / grid;

    float acc[8][4] = {};

    prefetchA(0, bid, grid, M, A, sA_u32, tid);

    for (int it = 0; it < nIter; ++it) {
        if (it) __syncthreads();
        if (it + 1 < nIter) {
            prefetchA(it + 1, bid, grid, M, A, sA_u32, tid);
            CP_WAIT(1);
        } else {
            CP_WAIT(0);
        }
        __syncthreads();

        const uint8_t* aS = sA + (it & 1) * ASZ;

#pragma unroll
        for (int s = 0; s < 16; ++s) {          // 16 k8 steps
            const int r0b = (warp_m * 16 + qrow) * ASTR + (s * 8 + lm4) * 4;
            const int r8b = r0b + 8 * ASTR;
            uint32_t a0 = f2tf32(*reinterpret_cast<const float*>(aS + r0b));
            uint32_t a1 = f2tf32(*reinterpret_cast<const float*>(aS + r8b));
            uint32_t a2 = f2tf32(*reinterpret_cast<const float*>(aS + r0b + 16));
            uint32_t a3 = f2tf32(*reinterpret_cast<const float*>(aS + r8b + 16));
            const int gkb = s * 32 + lm4 * 8;
#pragma unroll
            for (int j = 0; j < 8; ++j) {
                const int nb = (warp_n * 64 + j * 8 + qrow) * BSTR + gkb;
                uint2 b = *reinterpret_cast<const uint2*>(sB + nb);
                mma_tf32(acc[j], a0, a1, a2, a3, b.x, b.y);
            }
        }

        {
            const int row0 = (bid + it * grid) << 7;
            const int r = row0 + warp_m * 16 + qrow;
#pragma unroll
            for (int j = 0; j < 8; ++j) {
                const int col = warp_n * 64 + j * 8 + lm4 * 2;
                float2 v0 = make_float2(acc[j][0], acc[j][1]);
                float2 v1 = make_float2(acc[j][2], acc[j][3]);
                if (EPI == 1) {
                    float2 bv = *reinterpret_cast<const float2*>(bias + col);
                    if (r < M) {
                        float2 a0v = __ldg(reinterpret_cast<const float2*>(
                                           addend + (size_t)r * 128 + col));
                        v0.x = fmaxf(v0.x + a0v.x + bv.x, 0.f);
                        v0.y = fmaxf(v0.y + a0v.y + bv.y, 0.f);
                    }
                    if (r + 8 < M) {
                        float2 a1v = __ldg(reinterpret_cast<const float2*>(
                                           addend + (size_t)(r + 8) * 128 + col));
                        v1.x = fmaxf(v1.x + a1v.x + bv.x, 0.f);
                        v1.y = fmaxf(v1.y + a1v.y + bv.y, 0.f);
                    }
                }
                if (r < M)
                    *reinterpret_cast<float2*>(out + (size_t)r * 128 + col) = v0;
                if (r + 8 < M)
                    *reinterpret_cast<float2*>(out + (size_t)(r + 8) * 128 + col) = v1;
                acc[j][0] = acc[j][1] = acc[j][2] = acc[j][3] = 0.f;
            }
        }
    }
}

// ===========================================================================
// CSR build: histogram -> scan1 -> scan3(+folded block-sum scan) -> slot fill
// ===========================================================================
__global__ void zero_deg_kernel(int* deg, int n) {
    int i = blockIdx.x * blockDim.x + threadIdx.x;
    if (i < n) deg[i] = 0;
}

__global__ void hist_kernel(const int* __restrict__ ei, int* __restrict__ deg, int E) {
    int e = blockIdx.x * blockDim.x + threadIdx.x;
    if (e >= E) return;
    int d = __ldg(&ei[E + e]);
    if ((unsigned)d < NN) atomicAdd(&deg[d], 1);
}

__global__ void scan1_kernel(const int* __restrict__ deg, int* __restrict__ excl,
                             int* __restrict__ bsum, int n) {
    __shared__ int sh[SCAN_BLK];
    int b = blockIdx.x;
    int i = b * SCAN_BLK + threadIdx.x;
    int v = (i < n) ? deg[i] : 0;
    sh[threadIdx.x] = v;
    __syncthreads();
#pragma unroll
    for (int off = 1; off < SCAN_BLK; off <<= 1) {
        int t = (threadIdx.x >= off) ? sh[threadIdx.x - off] : 0;
        __syncthreads();
        sh[threadIdx.x] += t;
        __syncthreads();
    }
    if (i < n) excl[i] = sh[threadIdx.x] - v;
    if (threadIdx.x == SCAN_BLK - 1) bsum[b] = sh[SCAN_BLK - 1];
}

// scan3 with the block-sum scan folded in: every block redundantly scans the
// <=256 block sums in smem (cheap), then applies the exclusive block offset.
__global__ void scan3_kernel(const int* __restrict__ excl, const int* __restrict__ bsum,
                             int* __restrict__ rowptr, int* __restrict__ cursor,
                             int n, int total, int nb) {
    __shared__ int sh[256];
    int t = threadIdx.x;
    int v = (t < nb) ? __ldg(&bsum[t]) : 0;
    sh[t] = v;
    __syncthreads();
#pragma unroll
    for (int off = 1; off < 256; off <<= 1) {
        int u = (t >= off) ? sh[t - off] : 0;
        __syncthreads();
        sh[t] += u;
        __syncthreads();
    }
    // sh = inclusive scan of bsum
    int i = blockIdx.x * blockDim.x + t;
    if (i < n) {
        int b = i / SCAN_BLK;
        int boffb = sh[b] - __ldg(&bsum[b]);   // exclusive offset
        int val = excl[i] + boffb;
        rowptr[i] = val;
        cursor[i] = val;
    }
    if (i == 0) rowptr[n] = total;
}

// slot fill: 1 edge per thread (max latency-hiding parallelism for ATOMG)
__global__ void fill_kernel(const int* __restrict__ ei, int* __restrict__ cursor,
                            int* __restrict__ srcs, int E) {
    int e = blockIdx.x * blockDim.x + threadIdx.x;
    if (e >= E) return;
    int s = __ldg(&ei[e]);
    int d = __ldg(&ei[E + e]);
    if ((unsigned)s >= NN || (unsigned)d >= NN) return;
    int slot = atomicAdd(&cursor[d], 1);
    srcs[slot] = s;
}

// ===========================================================================
// agg1: warp per node, mean of neighbor x rows (no atomics; L2-roofline bound)
// ===========================================================================
__global__ void agg1_kernel(const float* __restrict__ x,
                            const int* __restrict__ rowptr,
                            const int* __restrict__ srcs,
                            float* __restrict__ agg) {
    int gid = blockIdx.x * blockDim.x + threadIdx.x;
    int n = gid >> 5, lane = gid & 31;
    if (n >= NN) return;
    int beg = __ldg(&rowptr[n]), end = __ldg(&rowptr[n + 1]);
    float4 acc = make_float4(0.f, 0.f, 0.f, 0.f);
    for (int i = beg; i < end; ++i) {
        int s = __ldg(&srcs[i]);
        float4 v = __ldg(reinterpret_cast<const float4*>(x + (size_t)s * 128) + lane);
        acc.x += v.x; acc.y += v.y; acc.z += v.z; acc.w += v.w;
    }
    float sc = 1.f / fmaxf((float)(end - beg), 1.f);
    acc.x *= sc; acc.y *= sc; acc.z *= sc; acc.w *= sc;
    reinterpret_cast<float4*>(agg + (size_t)n * 128)[lane] = acc;
}

// layer-2 aggregation of p fused with combine: z = mean_p + q + b2
__global__ void agg2z_kernel(const float* __restrict__ pq,
                             const int* __restrict__ rowptr,
                             const int* __restrict__ srcs,
                             const float* __restrict__ b2,
                             float* __restrict__ z) {
    int gid = blockIdx.x * blockDim.x + threadIdx.x;
    int n = gid >> 5, lane = gid & 31;
    if (n >= NN) return;
    int beg = __ldg(&rowptr[n]), end = __ldg(&rowptr[n + 1]);
    float2 acc = make_float2(0.f, 0.f);
    for (int i = beg; i < end; ++i) {
        int s = __ldg(&srcs[i]);
        float2 v = __ldg(reinterpret_cast<const float2*>(pq + (size_t)s * 128) + lane);
        acc.x += v.x; acc.y += v.y;
    }
    float sc = 1.f / fmaxf((float)(end - beg), 1.f);
    float2 q = __ldg(reinterpret_cast<const float2*>(pq + (size_t)n * 128 + 64) + lane);
    float2 bv = *reinterpret_cast<const float2*>(b2 + lane * 2);
    float2 r;
    r.x = fmaf(acc.x, sc, q.x + bv.x);
    r.y = fmaf(acc.y, sc, q.y + bv.y);
    *reinterpret_cast<float2*>(z + (size_t)n * 64 + lane * 2) = r;
}

// Decode: half-warp per pair, float4 loads
__global__ void decode_kernel(const float* __restrict__ z,
                              const int* __restrict__ eli,
                              float* __restrict__ out, int L) {
    int gid = blockIdx.x * blockDim.x + threadIdx.x;
    int e = gid >> 4;
    int l = gid & 15;
    if (e >= L) return;
    int a = __ldg(&eli[e]);
    int b = __ldg(&eli[L + e]);
    float s = 0.f;
    if ((unsigned)a < NN && (unsigned)b < NN) {
        float4 va = __ldg(reinterpret_cast<const float4*>(z + (size_t)a * 64) + l);
        float4 vb = __ldg(reinterpret_cast<const float4*>(z + (size_t)b * 64) + l);
        s = va.x * vb.x + va.y * vb.y + va.z * vb.z + va.w * vb.w;
    }
#pragma unroll
    for (int off = 8; off > 0; off >>= 1)
        s += __shfl_xor_sync(0xFFFFFFFFu, s, off);
    if (l == 0) out[e] = s;
}

// ===========================================================================
extern "C" void kernel_launch(void* const* d_in, const int* in_sizes, int n_in,
                              void* d_out, int out_size) {
    const float* x   = (const float*)d_in[0];
    const int*   ei  = (const int*)d_in[1];
    const int*   eli = (const int*)d_in[2];
    const float* W1l = (const float*)d_in[3];
    const float* b1  = (const float*)d_in[4];
    const float* W1r = (const float*)d_in[5];
    const float* W2l = (const float*)d_in[6];
    const float* b2  = (const float*)d_in[7];
    const float* W2r = (const float*)d_in[8];
    float* out = (float*)d_out;

    float *agg, *hpre, *h, *pq, *z;
    int *deg, *excl, *bsum, *rowptr, *cursor, *srcs;
    cudaGetSymbolAddress((void**)&agg,  g_agg);
    cudaGetSymbolAddress((void**)&hpre, g_hpre);
    cudaGetSymbolAddress((void**)&h,    g_h);
    cudaGetSymbolAddress((void**)&pq,   g_pq);
    cudaGetSymbolAddress((void**)&z,    g_z);
    cudaGetSymbolAddress((void**)&deg,  g_deg);
    cudaGetSymbolAddress((void**)&excl, g_excl);
    cudaGetSymbolAddress((void**)&bsum, g_bsum);
    cudaGetSymbolAddress((void**)&rowptr, g_rowptr);
    cudaGetSymbolAddress((void**)&cursor, g_cursor);
    cudaGetSymbolAddress((void**)&srcs, g_srcs);

    // smem: B tf32 (69632) + 2 A stages (135168) + pad
    const int smemB = SB + 2 * ASZ + 256;
    cudaFuncSetAttribute(pgemmB_kernel<0>, cudaFuncAttributeMaxDynamicSharedMemorySize, smemB);
    cudaFuncSetAttribute(pgemmB_kernel<1>, cudaFuncAttributeMaxDynamicSharedMemorySize, smemB);
    const int PGRID = 148;

    // Fork a side stream off the capture stream (graph fork-join pattern).
    cudaStream_t side;
    cudaStreamCreateWithFlags(&side, cudaStreamNonBlocking);
    cudaEvent_t ev_fork, ev_join;
    cudaEventCreateWithFlags(&ev_fork, cudaEventDisableTiming);
    cudaEventCreateWithFlags(&ev_join, cudaEventDisableTiming);

    cudaEventRecord(ev_fork, 0);
    cudaStreamWaitEvent(side, ev_fork, 0);

    // ---- side stream: self-term GEMM  h_pre = x @ W1r^T ----
    pgemmB_kernel<0><<<PGRID, 512, smemB, side>>>(
        x, W1r, W1r + 64 * 128, nullptr, nullptr, hpre, NN);
    cudaEventRecord(ev_join, side);

    // ---- main stream: CSR build + layer-1 aggregation (independent) ----
    zero_deg_kernel<<<(NN + 255) / 256, 256>>>(deg, NN);
    hist_kernel<<<(NE + 255) / 256, 256>>>(ei, deg, NE);
    scan1_kernel<<<NSCAN, SCAN_BLK>>>(deg, excl, bsum, NN);
    scan3_kernel<<<(NN + 255) / 256, 256>>>(excl, bsum, rowptr, cursor, NN, NE, NSCAN);
    fill_kernel<<<(NE + 255) / 256, 256>>>(ei, cursor, srcs, NE);
    agg1_kernel<<<(NN * 32 + 255) / 256, 256>>>(x, rowptr, srcs, agg);

    // ---- join, then layer-1 neighbor GEMM with fused self/bias/relu ----
    cudaStreamWaitEvent(0, ev_join, 0);
    pgemmB_kernel<1><<<PGRID, 512, smemB>>>(
        agg, W1l, W1l + 64 * 128, hpre, b1, h, NN);

    // ---- Layer 2 (projection-before-aggregation) ----
    pgemmB_kernel<0><<<PGRID, 512, smemB>>>(h, W2l, W2r, nullptr, nullptr, pq, NN);
    agg2z_kernel<<<(NN * 32 + 255) / 256, 256>>>(pq, rowptr, srcs, b2, z);

    // ---- Decode ----
    decode_kernel<<<(NL * 16 + 255) / 256, 256>>>(z, eli, out, NL);
}

// round 16
// speedup vs baseline: 1.0382x; 1.0058x over previous
#include <cuda_runtime.h>
#include <cuda_bf16.h>
#include <cstdint>

#define NN 100000
#define NE 640000
#define NL 100000
#define SCAN_BLK 512
#define NSCAN ((NN + SCAN_BLK - 1) / SCAN_BLK)

// Scratch (device globals: allocation-free rule)
__device__ float g_agg[(size_t)NN * 128];     // layer-1 mean aggregate (tf32-rounded)
__device__ float g_hpre[(size_t)NN * 128];    // x @ W1r^T (self term)
__device__ float g_h[(size_t)NN * 128];       // tf32-rounded
__device__ float g_pq[(size_t)NN * 128];      // [p | q] = h @ [W2l | W2r]^T
__device__ float g_z[(size_t)NN * 64];
// CSR scratch
__device__ int g_deg[NN];
__device__ int g_excl[NN];
__device__ int g_bsum[NSCAN];
__device__ int g_rowptr[NN + 1];
__device__ int g_cursor[NN];
__device__ int g_srcs[NE];

// ---------------------------------------------------------------------------
__device__ __forceinline__ uint32_t smem_u32(const void* p) {
    uint32_t a;
    asm("{ .reg .u64 t; cvta.to.shared.u64 t, %1; cvt.u32.u64 %0, t; }" : "=r"(a) : "l"(p));
    return a;
}

__device__ __forceinline__ void cp_async16(uint32_t saddr, const void* gaddr, int src_size) {
    asm volatile("cp.async.cg.shared.global [%0], [%1], 16, %2;"
                 :: "r"(saddr), "l"(gaddr), "r"(src_size) : "memory");
}
#define CP_COMMIT() asm volatile("cp.async.commit_group;" ::: "memory")
#define CP_WAIT(N)  asm volatile("cp.async.wait_group %0;" :: "n"(N) : "memory")

__device__ __forceinline__ uint32_t f2tf32(float v) {
    uint32_t t;
    asm("cvt.rna.tf32.f32 %0, %1;" : "=r"(t) : "f"(v));
    return t;
}
__device__ __forceinline__ float round_tf32(float v) {
    return __uint_as_float(f2tf32(v));
}

// m16n8k8 tf32 mma, fp32 accumulate in place (row.col)
__device__ __forceinline__ void mma_tf32(float* c, uint32_t a0, uint32_t a1,
                                         uint32_t a2, uint32_t a3,
                                         uint32_t b0, uint32_t b1) {
    asm volatile(
        "mma.sync.aligned.m16n8k8.row.col.f32.tf32.tf32.f32 "
        "{%0,%1,%2,%3}, {%4,%5,%6,%7}, {%8,%9}, {%0,%1,%2,%3};"
        : "+f"(c[0]), "+f"(c[1]), "+f"(c[2]), "+f"(c[3])
        : "r"(a0), "r"(a1), "r"(a2), "r"(a3), "r"(b0), "r"(b1));
}

// A stage: K=128 fp32 row (512B) + 16B pad (528 -> LDS.32 conflict-free)
#define ASTR 528
#define ASZ  (128 * ASTR)   // one stage = 67584 B
// B tile: K=128 tf32 row (512B) + 32B pad (544 -> phase-conflict-free LDS.64)
#define BSTR 544
#define SB   (128 * BSTR)   // 69632 B

// Weight tile conversion into smem: tf32, per-k8-group word order
// (k0,k4)(k1,k5)(k2,k6)(k3,k7) so the m16n8k8 B fragment {k, k+4} is one LDS.64.
__device__ __forceinline__ void convert_weights(
    uint8_t* sB,
    const float* __restrict__ Wa, const float* __restrict__ Wb,
    int tid, int nthreads)
{
    for (int idx = tid; idx < 128 * 32; idx += nthreads) {
        int row = idx >> 5;
        int k = (idx & 31) * 4;                 // 0,4,8,...,124
        const float* wsrc = ((row < 64) ? (Wa + (size_t)row * 128)
                                        : (Wb + (size_t)(row - 64) * 128)) + k;
        float4 v = __ldg(reinterpret_cast<const float4*>(wsrc));
        uint32_t t0 = f2tf32(v.x), t1 = f2tf32(v.y), t2 = f2tf32(v.z), t3 = f2tf32(v.w);
        const int base = row * BSTR + (k >> 3) * 32;   // 32B per k8 group
        const int half = (k & 7) >> 2;                 // 0: b0 slots, 1: b1 slots
        *reinterpret_cast<uint32_t*>(sB + base + 0 * 8 + half * 4) = t0;
        *reinterpret_cast<uint32_t*>(sB + base + 1 * 8 + half * 4) = t1;
        *reinterpret_cast<uint32_t*>(sB + base + 2 * 8 + half * 4) = t2;
        *reinterpret_cast<uint32_t*>(sB + base + 3 * 8 + half * 4) = t3;
    }
}

// ===========================================================================
// Persistent K=128 TF32 GEMM: out[m, 0:128] = epi( A[m,:] @ W^T )
// W rows: row<64 from Wa, else Wb. EPI 0: identity. EPI 1: relu(acc +
// addend + bias), output rounded to tf32 (consumer is a CVT=0 GEMM A-side).
// CVT 1: A raw fp32, cvt in inner loop. CVT 0: A pre-rounded tf32, raw loads.
// 512 threads / 16 warps, warp tile 16x64, cp.async 2-stage full-tile pipeline.
// ===========================================================================
__device__ __forceinline__ void prefetchA(
    int it, int bid, int grid, int M,
    const float* __restrict__ A, uint32_t sA_u32, int tid)
{
    const int row0 = (bid + it * grid) << 7;
    const uint32_t abase = sA_u32 + (it & 1) * ASZ;
    const float* gbase = A + (size_t)row0 * 128;
#pragma unroll
    for (int s = 0; s < 8; ++s) {
        int seg = s * 512 + tid;
        int r = seg >> 5, c = seg & 31;
        bool val = (row0 + r) < M;
        const float* g = gbase + (val ? ((size_t)r * 128 + c * 4) : 0);
        cp_async16(abase + r * ASTR + c * 16, g, val ? 16 : 0);
    }
    CP_COMMIT();
}

template <int EPI, int CVT>
__global__ void __launch_bounds__(512, 1)
pgemmB_kernel(const float* __restrict__ A,
              const float* __restrict__ Wa, const float* __restrict__ Wb,
              const float* __restrict__ addend, const float* __restrict__ bias,
              float* __restrict__ out, int M)
{
    extern __shared__ uint8_t smem[];
    uint8_t* sB = smem;
    uint8_t* sA = smem + SB;

    const int tid = threadIdx.x, lane = tid & 31, wid = tid >> 5;
    const int warp_m = wid & 7, warp_n = wid >> 3;
    const int qrow = lane >> 2, lm4 = lane & 3;
    const int bid = blockIdx.x, grid = gridDim.x;
    const uint32_t sA_u32 = smem_u32(smem) + SB;

    convert_weights(sB, Wa, Wb, tid, 512);

    const int ntiles = (M + 127) >> 7;
    if (bid >= ntiles) return;
    const int nIter = (ntiles - bid + grid - 1) / grid;

    float acc[8][4] = {};

    prefetchA(0, bid, grid, M, A, sA_u32, tid);

    for (int it = 0; it < nIter; ++it) {
        if (it) __syncthreads();
        if (it + 1 < nIter) {
            prefetchA(it + 1, bid, grid, M, A, sA_u32, tid);
            CP_WAIT(1);
        } else {
            CP_WAIT(0);
        }
        __syncthreads();

        const uint8_t* aS = sA + (it & 1) * ASZ;

#pragma unroll
        for (int s = 0; s < 16; ++s) {          // 16 k8 steps
            const int r0b = (warp_m * 16 + qrow) * ASTR + (s * 8 + lm4) * 4;
            const int r8b = r0b + 8 * ASTR;
            uint32_t a0, a1, a2, a3;
            if (CVT) {
                a0 = f2tf32(*reinterpret_cast<const float*>(aS + r0b));
                a1 = f2tf32(*reinterpret_cast<const float*>(aS + r8b));
                a2 = f2tf32(*reinterpret_cast<const float*>(aS + r0b + 16));
                a3 = f2tf32(*reinterpret_cast<const float*>(aS + r8b + 16));
            } else {
                a0 = *reinterpret_cast<const uint32_t*>(aS + r0b);
                a1 = *reinterpret_cast<const uint32_t*>(aS + r8b);
                a2 = *reinterpret_cast<const uint32_t*>(aS + r0b + 16);
                a3 = *reinterpret_cast<const uint32_t*>(aS + r8b + 16);
            }
            const int gkb = s * 32 + lm4 * 8;
#pragma unroll
            for (int j = 0; j < 8; ++j) {
                const int nb = (warp_n * 64 + j * 8 + qrow) * BSTR + gkb;
                uint2 b = *reinterpret_cast<const uint2*>(sB + nb);
                mma_tf32(acc[j], a0, a1, a2, a3, b.x, b.y);
            }
        }

        {
            const int row0 = (bid + it * grid) << 7;
            const int r = row0 + warp_m * 16 + qrow;
#pragma unroll
            for (int j = 0; j < 8; ++j) {
                const int col = warp_n * 64 + j * 8 + lm4 * 2;
                float2 v0 = make_float2(acc[j][0], acc[j][1]);
                float2 v1 = make_float2(acc[j][2], acc[j][3]);
                if (EPI == 1) {
                    float2 bv = *reinterpret_cast<const float2*>(bias + col);
                    if (r < M) {
                        float2 a0v = __ldg(reinterpret_cast<const float2*>(
                                           addend + (size_t)r * 128 + col));
                        v0.x = round_tf32(fmaxf(v0.x + a0v.x + bv.x, 0.f));
                        v0.y = round_tf32(fmaxf(v0.y + a0v.y + bv.y, 0.f));
                    }
                    if (r + 8 < M) {
                        float2 a1v = __ldg(reinterpret_cast<const float2*>(
                                           addend + (size_t)(r + 8) * 128 + col));
                        v1.x = round_tf32(fmaxf(v1.x + a1v.x + bv.x, 0.f));
                        v1.y = round_tf32(fmaxf(v1.y + a1v.y + bv.y, 0.f));
                    }
                }
                if (r < M)
                    *reinterpret_cast<float2*>(out + (size_t)r * 128 + col) = v0;
                if (r + 8 < M)
                    *reinterpret_cast<float2*>(out + (size_t)(r + 8) * 128 + col) = v1;
                acc[j][0] = acc[j][1] = acc[j][2] = acc[j][3] = 0.f;
            }
        }
    }
}

// ===========================================================================
// CSR build: histogram -> scan1 -> scan3(+folded block-sum scan) -> slot fill
// ===========================================================================
__global__ void zero_deg_kernel(int* deg, int n) {
    int i = blockIdx.x * blockDim.x + threadIdx.x;
    if (i < n) deg[i] = 0;
}

__global__ void hist_kernel(const int* __restrict__ ei, int* __restrict__ deg, int E) {
    int e = blockIdx.x * blockDim.x + threadIdx.x;
    if (e >= E) return;
    int d = __ldg(&ei[E + e]);
    if ((unsigned)d < NN) atomicAdd(&deg[d], 1);
}

__global__ void scan1_kernel(const int* __restrict__ deg, int* __restrict__ excl,
                             int* __restrict__ bsum, int n) {
    __shared__ int sh[SCAN_BLK];
    int b = blockIdx.x;
    int i = b * SCAN_BLK + threadIdx.x;
    int v = (i < n) ? deg[i] : 0;
    sh[threadIdx.x] = v;
    __syncthreads();
#pragma unroll
    for (int off = 1; off < SCAN_BLK; off <<= 1) {
        int t = (threadIdx.x >= off) ? sh[threadIdx.x - off] : 0;
        __syncthreads();
        sh[threadIdx.x] += t;
        __syncthreads();
    }
    if (i < n) excl[i] = sh[threadIdx.x] - v;
    if (threadIdx.x == SCAN_BLK - 1) bsum[b] = sh[SCAN_BLK - 1];
}

// scan3 with the block-sum scan folded in
__global__ void scan3_kernel(const int* __restrict__ excl, const int* __restrict__ bsum,
                             int* __restrict__ rowptr, int* __restrict__ cursor,
                             int n, int total, int nb) {
    __shared__ int sh[256];
    int t = threadIdx.x;
    int v = (t < nb) ? __ldg(&bsum[t]) : 0;
    sh[t] = v;
    __syncthreads();
#pragma unroll
    for (int off = 1; off < 256; off <<= 1) {
        int u = (t >= off) ? sh[t - off] : 0;
        __syncthreads();
        sh[t] += u;
        __syncthreads();
    }
    int i = blockIdx.x * blockDim.x + t;
    if (i < n) {
        int b = i / SCAN_BLK;
        int boffb = sh[b] - __ldg(&bsum[b]);
        int val = excl[i] + boffb;
        rowptr[i] = val;
        cursor[i] = val;
    }
    if (i == 0) rowptr[n] = total;
}

// slot fill: 1 edge per thread (max latency-hiding parallelism for ATOMG)
__global__ void fill_kernel(const int* __restrict__ ei, int* __restrict__ cursor,
                            int* __restrict__ srcs, int E) {
    int e = blockIdx.x * blockDim.x + threadIdx.x;
    if (e >= E) return;
    int s = __ldg(&ei[e]);
    int d = __ldg(&ei[E + e]);
    if ((unsigned)s >= NN || (unsigned)d >= NN) return;
    int slot = atomicAdd(&cursor[d], 1);
    srcs[slot] = s;
}

// ===========================================================================
// agg1: warp per node, mean of neighbor x rows; output rounded to tf32
// (its only consumer is GEMM1's CVT=0 A side).
// ===========================================================================
__global__ void agg1_kernel(const float* __restrict__ x,
                            const int* __restrict__ rowptr,
                            const int* __restrict__ srcs,
                            float* __restrict__ agg) {
    int gid = blockIdx.x * blockDim.x + threadIdx.x;
    int n = gid >> 5, lane = gid & 31;
    if (n >= NN) return;
    int beg = __ldg(&rowptr[n]), end = __ldg(&rowptr[n + 1]);
    float4 acc = make_float4(0.f, 0.f, 0.f, 0.f);
    for (int i = beg; i < end; ++i) {
        int s = __ldg(&srcs[i]);
        float4 v = __ldg(reinterpret_cast<const float4*>(x + (size_t)s * 128) + lane);
        acc.x += v.x; acc.y += v.y; acc.z += v.z; acc.w += v.w;
    }
    float sc = 1.f / fmaxf((float)(end - beg), 1.f);
    acc.x = round_tf32(acc.x * sc);
    acc.y = round_tf32(acc.y * sc);
    acc.z = round_tf32(acc.z * sc);
    acc.w = round_tf32(acc.w * sc);
    reinterpret_cast<float4*>(agg + (size_t)n * 128)[lane] = acc;
}

// layer-2 aggregation of p fused with combine: z = mean_p + q + b2
__global__ void agg2z_kernel(const float* __restrict__ pq,
                             const int* __restrict__ rowptr,
                             const int* __restrict__ srcs,
                             const float* __restrict__ b2,
                             float* __restrict__ z) {
    int gid = blockIdx.x * blockDim.x + threadIdx.x;
    int n = gid >> 5, lane = gid & 31;
    if (n >= NN) return;
    int beg = __ldg(&rowptr[n]), end = __ldg(&rowptr[n + 1]);
    float2 acc = make_float2(0.f, 0.f);
    for (int i = beg; i < end; ++i) {
        int s = __ldg(&srcs[i]);
        float2 v = __ldg(reinterpret_cast<const float2*>(pq + (size_t)s * 128) + lane);
        acc.x += v.x; acc.y += v.y;
    }
    float sc = 1.f / fmaxf((float)(end - beg), 1.f);
    float2 q = __ldg(reinterpret_cast<const float2*>(pq + (size_t)n * 128 + 64) + lane);
    float2 bv = *reinterpret_cast<const float2*>(b2 + lane * 2);
    float2 r;
    r.x = fmaf(acc.x, sc, q.x + bv.x);
    r.y = fmaf(acc.y, sc, q.y + bv.y);
    *reinterpret_cast<float2*>(z + (size_t)n * 64 + lane * 2) = r;
}

// Decode: half-warp per pair, float4 loads
__global__ void decode_kernel(const float* __restrict__ z,
                              const int* __restrict__ eli,
                              float* __restrict__ out, int L) {
    int gid = blockIdx.x * blockDim.x + threadIdx.x;
    int e = gid >> 4;
    int l = gid & 15;
    if (e >= L) return;
    int a = __ldg(&eli[e]);
    int b = __ldg(&eli[L + e]);
    float s = 0.f;
    if ((unsigned)a < NN && (unsigned)b < NN) {
        float4 va = __ldg(reinterpret_cast<const float4*>(z + (size_t)a * 64) + l);
        float4 vb = __ldg(reinterpret_cast<const float4*>(z + (size_t)b * 64) + l);
        s = va.x * vb.x + va.y * vb.y + va.z * vb.z + va.w * vb.w;
    }
#pragma unroll
    for (int off = 8; off > 0; off >>= 1)
        s += __shfl_xor_sync(0xFFFFFFFFu, s, off);
    if (l == 0) out[e] = s;
}

// ===========================================================================
extern "C" void kernel_launch(void* const* d_in, const int* in_sizes, int n_in,
                              void* d_out, int out_size) {
    const float* x   = (const float*)d_in[0];
    const int*   ei  = (const int*)d_in[1];
    const int*   eli = (const int*)d_in[2];
    const float* W1l = (const float*)d_in[3];
    const float* b1  = (const float*)d_in[4];
    const float* W1r = (const float*)d_in[5];
    const float* W2l = (const float*)d_in[6];
    const float* b2  = (const float*)d_in[7];
    const float* W2r = (const float*)d_in[8];
    float* out = (float*)d_out;

    float *agg, *hpre, *h, *pq, *z;
    int *deg, *excl, *bsum, *rowptr, *cursor, *srcs;
    cudaGetSymbolAddress((void**)&agg,  g_agg);
    cudaGetSymbolAddress((void**)&hpre, g_hpre);
    cudaGetSymbolAddress((void**)&h,    g_h);
    cudaGetSymbolAddress((void**)&pq,   g_pq);
    cudaGetSymbolAddress((void**)&z,    g_z);
    cudaGetSymbolAddress((void**)&deg,  g_deg);
    cudaGetSymbolAddress((void**)&excl, g_excl);
    cudaGetSymbolAddress((void**)&bsum, g_bsum);
    cudaGetSymbolAddress((void**)&rowptr, g_rowptr);
    cudaGetSymbolAddress((void**)&cursor, g_cursor);
    cudaGetSymbolAddress((void**)&srcs, g_srcs);

    // smem: B tf32 (69632) + 2 A stages (135168) + pad
    const int smemB = SB + 2 * ASZ + 256;
    cudaFuncSetAttribute((pgemmB_kernel<0, 1>), cudaFuncAttributeMaxDynamicSharedMemorySize, smemB);
    cudaFuncSetAttribute((pgemmB_kernel<1, 0>), cudaFuncAttributeMaxDynamicSharedMemorySize, smemB);
    cudaFuncSetAttribute((pgemmB_kernel<0, 0>), cudaFuncAttributeMaxDynamicSharedMemorySize, smemB);
    const int PGRID = 148;

    // Fork a side stream off the capture stream (graph fork-join pattern).
    cudaStream_t side;
    cudaStreamCreateWithFlags(&side, cudaStreamNonBlocking);
    cudaEvent_t ev_fork, ev_join;
    cudaEventCreateWithFlags(&ev_fork, cudaEventDisableTiming);
    cudaEventCreateWithFlags(&ev_join, cudaEventDisableTiming);

    cudaEventRecord(ev_fork, 0);
    cudaStreamWaitEvent(side, ev_fork, 0);

    // ---- side stream: self-term GEMM  h_pre = x @ W1r^T (A raw -> CVT=1) ----
    pgemmB_kernel<0, 1><<<PGRID, 512, smemB, side>>>(
        x, W1r, W1r + 64 * 128, nullptr, nullptr, hpre, NN);
    cudaEventRecord(ev_join, side);

    // ---- main stream: CSR build + layer-1 aggregation (independent) ----
    zero_deg_kernel<<<(NN + 255) / 256, 256>>>(deg, NN);
    hist_kernel<<<(NE + 255) / 256, 256>>>(ei, deg, NE);
    scan1_kernel<<<NSCAN, SCAN_BLK>>>(deg, excl, bsum, NN);
    scan3_kernel<<<(NN + 255) / 256, 256>>>(excl, bsum, rowptr, cursor, NN, NE, NSCAN);
    fill_kernel<<<(NE + 255) / 256, 256>>>(ei, cursor, srcs, NE);
    agg1_kernel<<<(NN * 32 + 255) / 256, 256>>>(x, rowptr, srcs, agg);

    // ---- join, then layer-1 neighbor GEMM (A pre-rounded -> CVT=0) ----
    cudaStreamWaitEvent(0, ev_join, 0);
    pgemmB_kernel<1, 0><<<PGRID, 512, smemB>>>(
        agg, W1l, W1l + 64 * 128, hpre, b1, h, NN);

    // ---- Layer 2 (h pre-rounded -> CVT=0) ----
    pgemmB_kernel<0, 0><<<PGRID, 512, smemB>>>(h, W2l, W2r, nullptr, nullptr, pq, NN);
    agg2z_kernel<<<(NN * 32 + 255) / 256, 256>>>(pq, rowptr, srcs, b2, z);

    // ---- Decode ----
    decode_kernel<<<(NL * 16 + 255) / 256, 256>>>(z, eli, out, NL);
}